// round 4
// baseline (speedup 1.0000x reference)
#include <cuda_runtime.h>

#define NBATCH 256
#define NTIME  256
#define NS     512   // state size
#define NE     128   // embedding
#define NALPH  128   // alphabet / output
#define FAN    640   // NE + NS
#define BT     (NBATCH * NTIME)

// ---- scratch (static __device__: allocation-free per harness rules) ----
__device__ float g_fin[BT * NS];        // fin[b][t][n]
__device__ float g_states[BT * NS];     // states[b][t][n]
__device__ float g_state[2][NBATCH * NS];  // ping-pong recurrent state
__device__ int   g_bar[NTIME];          // per-step grid barrier counters

// =====================================================================
// reset: zero barrier counters (fresh per launch -> graph-replay safe)
// =====================================================================
__global__ void reset_kernel() {
    int i = threadIdx.x;
    if (i < NTIME) g_bar[i] = 0;
}

// =====================================================================
// Phase 1: fin[bt][n] = dot(emb[w[bt]], W_in[n][0:128]) + b_in[n]
// grid (BT/64, NS/64), block 256, 64x64 tile, 4x4 micro, K=128
// =====================================================================
__global__ void fin_kernel(const int* __restrict__ w,
                           const float* __restrict__ emb,
                           const float* __restrict__ W_in,
                           const float* __restrict__ b_in) {
    __shared__ int   widx[64];
    __shared__ float As[64 * 36];   // pitch 36: conflict-free a-reads, f4-aligned stores
    __shared__ float Bs[64 * 33];   // pitch 33: conflict-free b-reads

    int tid = threadIdx.x;
    int tx = tid & 15, ty = tid >> 4;
    int bt0 = blockIdx.x * 64;
    int n0  = blockIdx.y * 64;

    if (tid < 64) widx[tid] = w[bt0 + tid];
    __syncthreads();

    float acc[4][4] = {};

    for (int kc = 0; kc < NE; kc += 32) {
        for (int s = tid; s < 512; s += 256) {
            int row = s >> 3, q = (s & 7) << 2;
            float4 v = *(const float4*)&emb[widx[row] * NE + kc + q];
            *(float4*)&As[row * 36 + q] = v;
        }
        for (int s = tid; s < 512; s += 256) {
            int row = s >> 3, q = (s & 7) << 2;
            float4 v = *(const float4*)&W_in[(n0 + row) * FAN + kc + q];
            float* d = &Bs[row * 33 + q];
            d[0] = v.x; d[1] = v.y; d[2] = v.z; d[3] = v.w;
        }
        __syncthreads();
        #pragma unroll
        for (int k = 0; k < 32; ++k) {
            float a[4], b[4];
            #pragma unroll
            for (int i = 0; i < 4; ++i) a[i] = As[(ty + 16 * i) * 36 + k];
            #pragma unroll
            for (int j = 0; j < 4; ++j) b[j] = Bs[(tx + 16 * j) * 33 + k];
            #pragma unroll
            for (int i = 0; i < 4; ++i)
                #pragma unroll
                for (int j = 0; j < 4; ++j)
                    acc[i][j] = fmaf(a[i], b[j], acc[i][j]);
        }
        __syncthreads();
    }

    #pragma unroll
    for (int i = 0; i < 4; ++i) {
        int r = bt0 + ty + 16 * i;
        #pragma unroll
        for (int j = 0; j < 4; ++j) {
            int c = n0 + tx + 16 * j;
            g_fin[r * NS + c] = acc[i][j] + b_in[c];
        }
    }
}

// =====================================================================
// Phase 2: persistent recurrent kernel.
// grid = 128 blocks (16 row-tiles of 16 batch rows x 8 col-tiles of 64
// state cols) -- all co-resident on 148 SMs. Block = 128 threads
// (tx 0..15 cols, ty 0..7 rows), 2x4 micro-tile.
// W_s slice (64 cols x 512 k) cached in SMEM for the whole kernel.
// =====================================================================
__global__ void __launch_bounds__(128, 1)
rnn_kernel(const float* __restrict__ W_in) {
    extern __shared__ float sm[];
    float* Bs = sm;                 // [64][518]  W_s slice (pitch 518)
    float* As = sm + 64 * 518;      // [16][520]  state tile (pitch 520)

    const int tid = threadIdx.x;
    const int tx = tid & 15;        // 0..15
    const int ty = tid >> 4;        // 0..7
    const int rowtile = blockIdx.x & 15;   // 16 row tiles
    const int coltile = blockIdx.x >> 4;   // 8 col tiles
    const int rb0 = rowtile * 16;
    const int cb0 = coltile * 64;

    // Load this block's W_s slice once: W_s[n][k] = W_in[n*FAN + NE + k]
    for (int it = 0; it < 64; ++it) {
        float4 v = *(const float4*)&W_in[(cb0 + it) * FAN + NE + 4 * tid];
        float* d = &Bs[it * 518 + 4 * tid];
        d[0] = v.x; d[1] = v.y; d[2] = v.z; d[3] = v.w;
    }
    __syncthreads();

    const float* bp0 = Bs + (tx)      * 518;
    const float* bp1 = Bs + (tx + 16) * 518;
    const float* bp2 = Bs + (tx + 32) * 518;
    const float* bp3 = Bs + (tx + 48) * 518;
    const float* ap0 = As + (ty)     * 520;
    const float* ap1 = As + (ty + 8) * 520;

    int cur = 0;
    for (int t = 0; t < NTIME; ++t) {
        float a00 = 0.f, a01 = 0.f, a02 = 0.f, a03 = 0.f;
        float a10 = 0.f, a11 = 0.f, a12 = 0.f, a13 = 0.f;

        if (t > 0) {
            // stage current state tile (L2-only loads: written by other SMs)
            for (int it = 0; it < 16; ++it) {
                float4 v = __ldcg((const float4*)&g_state[cur][(rb0 + it) * NS + 4 * tid]);
                *(float4*)&As[it * 520 + 4 * tid] = v;
            }
            __syncthreads();

            #pragma unroll 4
            for (int k = 0; k < NS; k += 2) {
                float2 va0 = *(const float2*)(ap0 + k);
                float2 va1 = *(const float2*)(ap1 + k);
                float2 vb0 = *(const float2*)(bp0 + k);
                float2 vb1 = *(const float2*)(bp1 + k);
                float2 vb2 = *(const float2*)(bp2 + k);
                float2 vb3 = *(const float2*)(bp3 + k);
                a00 = fmaf(va0.x, vb0.x, a00); a00 = fmaf(va0.y, vb0.y, a00);
                a01 = fmaf(va0.x, vb1.x, a01); a01 = fmaf(va0.y, vb1.y, a01);
                a02 = fmaf(va0.x, vb2.x, a02); a02 = fmaf(va0.y, vb2.y, a02);
                a03 = fmaf(va0.x, vb3.x, a03); a03 = fmaf(va0.y, vb3.y, a03);
                a10 = fmaf(va1.x, vb0.x, a10); a10 = fmaf(va1.y, vb0.y, a10);
                a11 = fmaf(va1.x, vb1.x, a11); a11 = fmaf(va1.y, vb1.y, a11);
                a12 = fmaf(va1.x, vb2.x, a12); a12 = fmaf(va1.y, vb2.y, a12);
                a13 = fmaf(va1.x, vb3.x, a13); a13 = fmaf(va1.y, vb3.y, a13);
            }
        }

        // epilogue: tanh(acc + fin_t), write next state + states log
        float accv[2][4] = {{a00, a01, a02, a03}, {a10, a11, a12, a13}};
        #pragma unroll
        for (int i = 0; i < 2; ++i) {
            int r = rb0 + ty + 8 * i;
            #pragma unroll
            for (int j = 0; j < 4; ++j) {
                int c = cb0 + tx + 16 * j;
                float v = tanhf(accv[i][j] + __ldcg(&g_fin[(r * NTIME + t) * NS + c]));
                g_state[cur ^ 1][r * NS + c] = v;
                g_states[(r * NTIME + t) * NS + c] = v;
            }
        }
        cur ^= 1;

        // grid barrier between steps
        if (t + 1 < NTIME) {
            __syncthreads();
            if (tid == 0) {
                __threadfence();                 // release my tile's writes
                atomicAdd(&g_bar[t], 1);
                while (*((volatile int*)&g_bar[t]) < 128) { }
            }
            __syncthreads();
        }
    }
}

// =====================================================================
// Phase 3: y[bt][a] = dot(states[bt], W_out[a]) + b_out[a]
// grid (BT/64, NALPH/64), block 256, 64x64 tile, 4x4 micro, K=512
// =====================================================================
__global__ void out_kernel(const float* __restrict__ W_out,
                           const float* __restrict__ b_out,
                           float* __restrict__ y) {
    __shared__ float As[64 * 36];
    __shared__ float Bs[64 * 33];

    int tid = threadIdx.x;
    int tx = tid & 15, ty = tid >> 4;
    int bt0 = blockIdx.x * 64;
    int a0  = blockIdx.y * 64;

    float acc[4][4] = {};

    for (int kc = 0; kc < NS; kc += 32) {
        for (int s = tid; s < 512; s += 256) {
            int row = s >> 3, q = (s & 7) << 2;
            float4 v = *(const float4*)&g_states[(bt0 + row) * NS + kc + q];
            *(float4*)&As[row * 36 + q] = v;
        }
        for (int s = tid; s < 512; s += 256) {
            int row = s >> 3, q = (s & 7) << 2;
            float4 v = *(const float4*)&W_out[(a0 + row) * NS + kc + q];
            float* d = &Bs[row * 33 + q];
            d[0] = v.x; d[1] = v.y; d[2] = v.z; d[3] = v.w;
        }
        __syncthreads();
        #pragma unroll
        for (int k = 0; k < 32; ++k) {
            float a[4], b[4];
            #pragma unroll
            for (int i = 0; i < 4; ++i) a[i] = As[(ty + 16 * i) * 36 + k];
            #pragma unroll
            for (int j = 0; j < 4; ++j) b[j] = Bs[(tx + 16 * j) * 33 + k];
            #pragma unroll
            for (int i = 0; i < 4; ++i)
                #pragma unroll
                for (int j = 0; j < 4; ++j)
                    acc[i][j] = fmaf(a[i], b[j], acc[i][j]);
        }
        __syncthreads();
    }

    #pragma unroll
    for (int i = 0; i < 4; ++i) {
        int r = bt0 + ty + 16 * i;
        #pragma unroll
        for (int j = 0; j < 4; ++j) {
            int c = a0 + tx + 16 * j;
            y[r * NALPH + c] = acc[i][j] + b_out[c];
        }
    }
}

// =====================================================================
// launch
// =====================================================================
extern "C" void kernel_launch(void* const* d_in, const int* in_sizes, int n_in,
                              void* d_out, int out_size) {
    const int*   w     = (const int*)  d_in[0];
    const float* emb   = (const float*)d_in[1];
    const float* W_in  = (const float*)d_in[2];
    const float* b_in  = (const float*)d_in[3];
    const float* W_out = (const float*)d_in[4];
    const float* b_out = (const float*)d_in[5];
    float* y = (float*)d_out;

    // persistent kernel needs 162 KB dynamic smem (opt-in above 48 KB)
    size_t rnn_smem = (size_t)(64 * 518 + 16 * 520) * sizeof(float);
    cudaFuncSetAttribute(rnn_kernel,
                         cudaFuncAttributeMaxDynamicSharedMemorySize,
                         (int)rnn_smem);

    reset_kernel<<<1, 256>>>();
    fin_kernel<<<dim3(BT / 64, NS / 64), 256>>>(w, emb, W_in, b_in);
    rnn_kernel<<<128, 128, rnn_smem>>>(W_in);
    out_kernel<<<dim3(BT / 64, NALPH / 64), 256>>>(W_out, b_out, y);
}

// round 5
// speedup vs baseline: 1.3946x; 1.3946x over previous
#include <cuda_runtime.h>

#define NBATCH 256
#define NTIME  256
#define NS     512   // state size
#define NE     128   // embedding
#define NALPH  128   // alphabet / output
#define FAN    640   // NE + NS
#define BT     (NBATCH * NTIME)

typedef unsigned long long u64;

// ---- scratch (static __device__: allocation-free per harness rules) ----
__device__ float g_fin[BT * NS];        // fin[(b*NTIME+t)*NS + n]
__device__ float g_states[BT * NS];     // states[(b*NTIME+t)*NS + n]  (also the recurrent state)
__device__ int   g_bar[NTIME];          // per-step grid barrier counters

// ---- packed fp32x2 helpers (Blackwell FFMA2) ----
__device__ __forceinline__ void fma2(u64& d, u64 a, u64 b) {
    asm("fma.rn.f32x2 %0, %1, %2, %0;" : "+l"(d) : "l"(a), "l"(b));
}
__device__ __forceinline__ float hadd2(u64 v) {
    float lo, hi;
    asm("mov.b64 {%0,%1}, %2;" : "=f"(lo), "=f"(hi) : "l"(v));
    return lo + hi;
}

// =====================================================================
// reset: zero barrier counters (fresh per launch -> graph-replay safe)
// =====================================================================
__global__ void reset_kernel() {
    int i = threadIdx.x;
    if (i < NTIME) g_bar[i] = 0;
}

// =====================================================================
// Phase 1: fin[bt][n] = dot(emb[w[bt]], W_in[n][0:128]) + b_in[n]
// grid (BT/64, NS/64), block 256, 64x64 tile, 4x4 micro, FFMA2 k-pairs
// =====================================================================
__global__ void fin_kernel(const int* __restrict__ w,
                           const float* __restrict__ emb,
                           const float* __restrict__ W_in,
                           const float* __restrict__ b_in) {
    __shared__ int   widx[64];
    __shared__ float As[64 * 36];   // pitch 36 (f4-aligned stores, bcast reads)
    __shared__ float Bs[64 * 34];   // pitch 34 (f2-aligned, conflict-free f2 reads)

    int tid = threadIdx.x;
    int tx = tid & 15, ty = tid >> 4;
    int bt0 = blockIdx.x * 64;
    int n0  = blockIdx.y * 64;

    if (tid < 64) widx[tid] = w[bt0 + tid];
    __syncthreads();

    u64 acc2[4][4] = {};

    for (int kc = 0; kc < NE; kc += 32) {
        for (int s = tid; s < 512; s += 256) {
            int row = s >> 3, q = (s & 7) << 2;
            float4 v = *(const float4*)&emb[widx[row] * NE + kc + q];
            *(float4*)&As[row * 36 + q] = v;
        }
        for (int s = tid; s < 512; s += 256) {
            int row = s >> 3, q = (s & 7) << 2;
            float4 v = *(const float4*)&W_in[(n0 + row) * FAN + kc + q];
            float2* d = (float2*)&Bs[row * 34 + q];
            d[0] = make_float2(v.x, v.y);
            d[1] = make_float2(v.z, v.w);
        }
        __syncthreads();
        #pragma unroll
        for (int k = 0; k < 32; k += 2) {
            u64 a2[4], b2[4];
            #pragma unroll
            for (int i = 0; i < 4; ++i) a2[i] = *(const u64*)&As[(ty + 16 * i) * 36 + k];
            #pragma unroll
            for (int j = 0; j < 4; ++j) b2[j] = *(const u64*)&Bs[(tx + 16 * j) * 34 + k];
            #pragma unroll
            for (int i = 0; i < 4; ++i)
                #pragma unroll
                for (int j = 0; j < 4; ++j)
                    fma2(acc2[i][j], a2[i], b2[j]);
        }
        __syncthreads();
    }

    #pragma unroll
    for (int i = 0; i < 4; ++i) {
        int r = bt0 + ty + 16 * i;
        #pragma unroll
        for (int j = 0; j < 4; ++j) {
            int c = n0 + tx + 16 * j;
            g_fin[r * NS + c] = hadd2(acc2[i][j]) + b_in[c];
        }
    }
}

// =====================================================================
// Phase 2: persistent recurrent kernel.
// grid = 128 blocks (16 row-tiles x 8 col-tiles), block = 128 threads,
// 2x4 micro-tile with packed f32x2 accumulators over k-pairs.
// W_s slice (64 cols x 512 k) lives in SMEM for the whole kernel.
// State is staged from the g_states log (no separate ping-pong buffer).
// fin(t+1) is prefetched between barrier arrive and poll.
// =====================================================================
__global__ void __launch_bounds__(128, 1)
rnn_kernel(const float* __restrict__ W_in) {
    extern __shared__ float sm[];
    float* Bs = sm;                 // [64][516]  W_s slice
    float* As = sm + 64 * 516;      // [16][520]  state tile

    const int tid = threadIdx.x;
    const int tx = tid & 15;        // 0..15
    const int ty = tid >> 4;        // 0..7
    const int rb0 = (blockIdx.x & 15) * 16;
    const int cb0 = (blockIdx.x >> 4) * 64;

    // Load W_s slice once: W_s[n][k] = W_in[n*FAN + NE + k]
    for (int it = 0; it < 64; ++it) {
        float4 v = *(const float4*)&W_in[(cb0 + it) * FAN + NE + 4 * tid];
        *(float4*)&Bs[it * 516 + 4 * tid] = v;
    }
    __syncthreads();

    const float* bp0 = Bs + (tx)      * 516;
    const float* bp1 = Bs + (tx + 16) * 516;
    const float* bp2 = Bs + (tx + 32) * 516;
    const float* bp3 = Bs + (tx + 48) * 516;
    const float* ap0 = As + (ty)     * 520;
    const float* ap1 = As + (ty + 8) * 520;

    const int r0 = rb0 + ty;
    const int r1 = rb0 + ty + 8;

    // prefetch fin for t = 0
    float ffin[2][4];
    #pragma unroll
    for (int j = 0; j < 4; ++j) {
        int c = cb0 + tx + 16 * j;
        ffin[0][j] = __ldcg(&g_fin[(r0 * NTIME + 0) * NS + c]);
        ffin[1][j] = __ldcg(&g_fin[(r1 * NTIME + 0) * NS + c]);
    }

    for (int t = 0; t < NTIME; ++t) {
        u64 acc[2][4] = {};

        if (t > 0) {
            #pragma unroll 4
            for (int k = 0; k < NS; k += 4) {
                ulonglong2 A0 = *(const ulonglong2*)(ap0 + k);
                ulonglong2 A1 = *(const ulonglong2*)(ap1 + k);
                ulonglong2 B0 = *(const ulonglong2*)(bp0 + k);
                ulonglong2 B1 = *(const ulonglong2*)(bp1 + k);
                ulonglong2 B2 = *(const ulonglong2*)(bp2 + k);
                ulonglong2 B3 = *(const ulonglong2*)(bp3 + k);
                fma2(acc[0][0], A0.x, B0.x); fma2(acc[0][0], A0.y, B0.y);
                fma2(acc[0][1], A0.x, B1.x); fma2(acc[0][1], A0.y, B1.y);
                fma2(acc[0][2], A0.x, B2.x); fma2(acc[0][2], A0.y, B2.y);
                fma2(acc[0][3], A0.x, B3.x); fma2(acc[0][3], A0.y, B3.y);
                fma2(acc[1][0], A1.x, B0.x); fma2(acc[1][0], A1.y, B0.y);
                fma2(acc[1][1], A1.x, B1.x); fma2(acc[1][1], A1.y, B1.y);
                fma2(acc[1][2], A1.x, B2.x); fma2(acc[1][2], A1.y, B2.y);
                fma2(acc[1][3], A1.x, B3.x); fma2(acc[1][3], A1.y, B3.y);
            }
        }

        // epilogue: tanh(acc + fin_t) -> write to states log (this IS the state)
        #pragma unroll
        for (int i = 0; i < 2; ++i) {
            int r = (i == 0) ? r0 : r1;
            #pragma unroll
            for (int j = 0; j < 4; ++j) {
                int c = cb0 + tx + 16 * j;
                float v = tanhf(hadd2(acc[i][j]) + ffin[i][j]);
                g_states[(r * NTIME + t) * NS + c] = v;
            }
        }
        __syncthreads();          // all state STGs issued, As reads done

        if (t + 1 < NTIME) {
            if (tid == 0) {
                __threadfence();                 // release this tile's writes
                atomicAdd(&g_bar[t], 1);         // arrive
            }
            // -- overlapped with other blocks' arrival --
            #pragma unroll
            for (int j = 0; j < 4; ++j) {
                int c = cb0 + tx + 16 * j;
                ffin[0][j] = __ldcg(&g_fin[(r0 * NTIME + t + 1) * NS + c]);
                ffin[1][j] = __ldcg(&g_fin[(r1 * NTIME + t + 1) * NS + c]);
            }
            if (tid == 0) {
                while (*((volatile int*)&g_bar[t]) < 128) { }
            }
            __syncthreads();

            // stage states[t] (written by all blocks) for step t+1
            #pragma unroll
            for (int it = 0; it < 16; ++it) {
                float4 v = __ldcg((const float4*)
                    &g_states[((rb0 + it) * NTIME + t) * NS + 4 * tid]);
                *(float4*)&As[it * 520 + 4 * tid] = v;
            }
            __syncthreads();
        }
    }
}

// =====================================================================
// Phase 3: y[bt][a] = dot(states[bt], W_out[a]) + b_out[a]
// grid (BT/64, NALPH/64), block 256, 64x64 tile, FFMA2 k-pairs, K=512
// =====================================================================
__global__ void out_kernel(const float* __restrict__ W_out,
                           const float* __restrict__ b_out,
                           float* __restrict__ y) {
    __shared__ float As[64 * 36];
    __shared__ float Bs[64 * 34];

    int tid = threadIdx.x;
    int tx = tid & 15, ty = tid >> 4;
    int bt0 = blockIdx.x * 64;
    int a0  = blockIdx.y * 64;

    u64 acc2[4][4] = {};

    for (int kc = 0; kc < NS; kc += 32) {
        for (int s = tid; s < 512; s += 256) {
            int row = s >> 3, q = (s & 7) << 2;
            float4 v = *(const float4*)&g_states[(bt0 + row) * NS + kc + q];
            *(float4*)&As[row * 36 + q] = v;
        }
        for (int s = tid; s < 512; s += 256) {
            int row = s >> 3, q = (s & 7) << 2;
            float4 v = *(const float4*)&W_out[(a0 + row) * NS + kc + q];
            float2* d = (float2*)&Bs[row * 34 + q];
            d[0] = make_float2(v.x, v.y);
            d[1] = make_float2(v.z, v.w);
        }
        __syncthreads();
        #pragma unroll
        for (int k = 0; k < 32; k += 2) {
            u64 a2[4], b2[4];
            #pragma unroll
            for (int i = 0; i < 4; ++i) a2[i] = *(const u64*)&As[(ty + 16 * i) * 36 + k];
            #pragma unroll
            for (int j = 0; j < 4; ++j) b2[j] = *(const u64*)&Bs[(tx + 16 * j) * 34 + k];
            #pragma unroll
            for (int i = 0; i < 4; ++i)
                #pragma unroll
                for (int j = 0; j < 4; ++j)
                    fma2(acc2[i][j], a2[i], b2[j]);
        }
        __syncthreads();
    }

    #pragma unroll
    for (int i = 0; i < 4; ++i) {
        int r = bt0 + ty + 16 * i;
        #pragma unroll
        for (int j = 0; j < 4; ++j) {
            int c = a0 + tx + 16 * j;
            y[r * NALPH + c] = hadd2(acc2[i][j]) + b_out[c];
        }
    }
}

// =====================================================================
// launch
// =====================================================================
extern "C" void kernel_launch(void* const* d_in, const int* in_sizes, int n_in,
                              void* d_out, int out_size) {
    const int*   w     = (const int*)  d_in[0];
    const float* emb   = (const float*)d_in[1];
    const float* W_in  = (const float*)d_in[2];
    const float* b_in  = (const float*)d_in[3];
    const float* W_out = (const float*)d_in[4];
    const float* b_out = (const float*)d_in[5];
    float* y = (float*)d_out;

    // persistent kernel needs ~162 KB dynamic smem (opt-in above 48 KB)
    size_t rnn_smem = (size_t)(64 * 516 + 16 * 520) * sizeof(float);
    cudaFuncSetAttribute(rnn_kernel,
                         cudaFuncAttributeMaxDynamicSharedMemorySize,
                         (int)rnn_smem);

    reset_kernel<<<1, 256>>>();
    fin_kernel<<<dim3(BT / 64, NS / 64), 256>>>(w, emb, W_in, b_in);
    rnn_kernel<<<128, 128, rnn_smem>>>(W_in);
    out_kernel<<<dim3(BT / 64, NALPH / 64), 256>>>(W_out, b_out, y);
}